// round 9
// baseline (speedup 1.0000x reference)
#include <cuda_runtime.h>
#include <cstdint>

#define BATCH 2
#define LSEQ 16384
#define BL (BATCH*LSEQ)      // 32768
#define DM 60
#define DI 120
#define DS 16
#define NC 128               // chunks
#define CL 128               // chunk length (NC*CL == LSEQ)

typedef unsigned long long ull;

// -------------------- scratch (static device memory, ~103 MB) --------------------
__device__ __align__(256) float g_ln   [BL*DM];
__device__ __align__(256) float g_xz   [BL*2*DI];
__device__ __align__(256) float g_xc   [BL*DI];
__device__ __align__(256) float g_xdb  [BL*36];
__device__ __align__(256) float g_delta[BL*DI];
__device__ __align__(256) float g_y    [BL*DI];
__device__ __align__(256) float g_h    [BL*DM];
__device__ __align__(256) float g_cH   [240*NC*16];
__device__ __align__(256) float g_cS   [240*NC];
__device__ __align__(256) float g_hini [240*NC*16];

// -------------------- f32x2 packed helpers --------------------
__device__ __forceinline__ ull pk2(float lo, float hi){
    ull r; asm("mov.b64 %0, {%1, %2};" : "=l"(r) : "f"(lo), "f"(hi)); return r;
}
__device__ __forceinline__ void fma2(ull& d, ull a, ull b){
    asm("fma.rn.f32x2 %0, %1, %2, %3;" : "=l"(d) : "l"(a), "l"(b), "l"(d));
}
__device__ __forceinline__ float2 upk2(ull v){
    float2 r; asm("mov.b64 {%0, %1}, %2;" : "=f"(r.x), "=f"(r.y) : "l"(v)); return r;
}

// -------------------- LayerNorm (warp per row, D=60) --------------------
__global__ void ln_kernel(const float* __restrict__ x, const float* __restrict__ w,
                          const float* __restrict__ b, float* __restrict__ out){
    int gw   = (blockIdx.x*blockDim.x + threadIdx.x) >> 5;
    int lane = threadIdx.x & 31;
    int nw   = (gridDim.x*blockDim.x) >> 5;
    for (int row = gw; row < BL; row += nw){
        const float* xr = x + (size_t)row*DM;
        float v0 = xr[lane];
        float v1 = (lane < DM-32) ? xr[lane+32] : 0.f;
        float s = v0 + v1;
        #pragma unroll
        for (int o=16;o;o>>=1) s += __shfl_xor_sync(0xffffffffu, s, o);
        float mu = s * (1.f/DM);
        float d0 = v0 - mu;
        float d1 = (lane < DM-32) ? (v1 - mu) : 0.f;
        float q = d0*d0 + d1*d1;
        #pragma unroll
        for (int o=16;o;o>>=1) q += __shfl_xor_sync(0xffffffffu, q, o);
        float rs = rsqrtf(q*(1.f/DM) + 1e-5f);
        float* orow = out + (size_t)row*DM;
        orow[lane] = d0*rs*w[lane] + b[lane];
        if (lane < DM-32) orow[lane+32] = d1*rs*w[lane+32] + b[lane+32];
    }
}

// -------------------- GEMM:  Y[M,N] = X[M,K] @ W[N,K]^T  --------------------
// 64x64 block tile, BK=16, 256 threads, 4x4 microtile, f32x2 FMA.
__global__ __launch_bounds__(256) void gemm_tn(
    const float* __restrict__ X, const float* __restrict__ W,
    float* __restrict__ Y, int M, int N, int K)
{
    __shared__ __align__(16) float xs[16][68];
    __shared__ __align__(16) float ws[16][68];
    int bm = blockIdx.x*64, bn = blockIdx.y*64;
    int tid = threadIdx.x;
    int tn = tid & 15, tm = tid >> 4;
    int r  = tid >> 2, kq = (tid & 3) << 2;
    ull acc[4][2] = {{0ull,0ull},{0ull,0ull},{0ull,0ull},{0ull,0ull}};

    for (int k0 = 0; k0 < K; k0 += 16){
        int gk = k0 + kq;
        float4 vx = make_float4(0.f,0.f,0.f,0.f);
        float4 vw = make_float4(0.f,0.f,0.f,0.f);
        int gm = bm + r;
        if (gm < M){
            const float* p = X + (size_t)gm*K + gk;
            if (gk + 3 < K) vx = *(const float4*)p;
            else {
                if (gk   < K) vx.x = p[0];
                if (gk+1 < K) vx.y = p[1];
                if (gk+2 < K) vx.z = p[2];
                if (gk+3 < K) vx.w = p[3];
            }
        }
        int gn = bn + r;
        if (gn < N){
            const float* p = W + (size_t)gn*K + gk;
            if (gk + 3 < K) vw = *(const float4*)p;
            else {
                if (gk   < K) vw.x = p[0];
                if (gk+1 < K) vw.y = p[1];
                if (gk+2 < K) vw.z = p[2];
                if (gk+3 < K) vw.w = p[3];
            }
        }
        __syncthreads();
        xs[kq+0][r]=vx.x; xs[kq+1][r]=vx.y; xs[kq+2][r]=vx.z; xs[kq+3][r]=vx.w;
        ws[kq+0][r]=vw.x; ws[kq+1][r]=vw.y; ws[kq+2][r]=vw.z; ws[kq+3][r]=vw.w;
        __syncthreads();
        #pragma unroll
        for (int kk=0; kk<16; kk++){
            float4 av = *(const float4*)&xs[kk][tm<<2];
            float4 bv = *(const float4*)&ws[kk][tn<<2];
            ull b0 = pk2(bv.x, bv.y);
            ull b1 = pk2(bv.z, bv.w);
            float a_[4] = {av.x, av.y, av.z, av.w};
            #pragma unroll
            for (int i=0;i<4;i++){
                ull ad = pk2(a_[i], a_[i]);
                fma2(acc[i][0], ad, b0);
                fma2(acc[i][1], ad, b1);
            }
        }
    }
    #pragma unroll
    for (int i=0;i<4;i++){
        int gm = bm + (tm<<2) + i;
        if (gm >= M) continue;
        float* yr = Y + (size_t)gm*N;
        #pragma unroll
        for (int jp=0;jp<2;jp++){
            float2 v = upk2(acc[i][jp]);
            int c0 = bn + (tn<<2) + jp*2;
            if (c0   < N) yr[c0]   = v.x;
            if (c0+1 < N) yr[c0+1] = v.y;
        }
    }
}

// -------------------- causal depthwise conv1d (D_CONV=4) + bias + SiLU --------------------
__global__ void conv1d_silu(const float* __restrict__ xz, const float* __restrict__ cw,
                            const float* __restrict__ cb, float* __restrict__ xc){
    __shared__ float s[67][120];
    int b = blockIdx.y;
    int start = blockIdx.x * 64;
    for (int idx = threadIdx.x; idx < 67*120; idx += 256){
        int j = idx/120, d = idx - j*120;
        int l = start + j - 3;
        s[j][d] = (l >= 0) ? xz[((size_t)(b*LSEQ + l))*240 + d] : 0.f;
    }
    __syncthreads();
    for (int idx = threadIdx.x; idx < 64*120; idx += 256){
        int i = idx/120, d = idx - i*120;
        const float* w = cw + d*4;
        float a = cb[d] + s[i][d]*w[0] + s[i+1][d]*w[1] + s[i+2][d]*w[2] + s[i+3][d]*w[3];
        float sg = 1.f/(1.f + __expf(-a));
        xc[((size_t)(b*LSEQ + start + i))*120 + d] = a*sg;
    }
}

// -------------------- dt projection + softplus --------------------
__global__ void dt_softplus(const float* __restrict__ xdb, const float* __restrict__ dtw,
                            const float* __restrict__ dtb, float* __restrict__ delta){
    int idx = blockIdx.x*256 + threadIdx.x;
    if (idx >= BL*120) return;
    int row = idx/120, d = idx - row*120;
    const float* xr = xdb + (size_t)row*36;
    float4 w = *(const float4*)(dtw + d*4);
    float sv = dtb[d] + xr[0]*w.x + xr[1]*w.y + xr[2]*w.z + xr[3]*w.w;
    delta[idx] = (sv > 20.f) ? sv : log1pf(__expf(sv));
}

// -------------------- selective scan, phase A: per-chunk local scan --------------------
// Warp layout: two 16-lane groups handle channels d=2p and d=2p+1 (same batch, same chunk),
// lane%16 = state index n.  Stores chunk-final h and sum(delta) over the chunk.
__global__ void scanA(const float* __restrict__ delta, const float* __restrict__ xc,
                      const float* __restrict__ xdb, const float* __restrict__ A_log,
                      float* __restrict__ cH, float* __restrict__ cS){
    int wid  = (blockIdx.x*256 + threadIdx.x) >> 5;
    int lane = threadIdx.x & 31;
    int grp = lane >> 4, n = lane & 15;
    if (wid >= 120*NC) return;
    int c  = wid & (NC-1);
    int bd = wid >> 7;                 // NC == 128
    int b = bd/60, dp = bd - b*60;
    int d = dp*2 + grp;
    float A = -expf(A_log[d*16 + n]);
    float h = 0.f, sd = 0.f;
    size_t row = (size_t)b*LSEQ + (size_t)c*CL;
    const float* pd = delta + row*120 + d;
    const float* px = xc    + row*120 + d;
    const float* pB = xdb   + row*36 + 4 + n;
    #pragma unroll 4
    for (int i=0;i<CL;i++){
        float dl = pd[i*120];
        float xv = px[i*120];
        float Bn = pB[i*36];
        float a  = __expf(A*dl);
        h  = __fmaf_rn(a, h, dl*Bn*xv);
        sd += dl;
    }
    int idx = (b*120 + d)*NC + c;
    cH[idx*16 + n] = h;
    if (n == 0) cS[idx] = sd;
}

// -------------------- scan phase B: cross-chunk prefix (tiny) --------------------
__global__ void scanB(const float* __restrict__ A_log, const float* __restrict__ cH,
                      const float* __restrict__ cS, float* __restrict__ hinit){
    int wid  = (blockIdx.x*256 + threadIdx.x) >> 5;
    int lane = threadIdx.x & 31;
    int grp = lane >> 4, n = lane & 15;
    if (wid >= 120) return;
    int b = wid/60, dp = wid - b*60;
    int d = dp*2 + grp;
    float A = -expf(A_log[d*16 + n]);
    float h = 0.f;
    int base = (b*120 + d)*NC;
    for (int c=0;c<NC;c++){
        hinit[(base+c)*16 + n] = h;
        float P = __expf(A * cS[base+c]);
        h = __fmaf_rn(P, h, cH[(base+c)*16 + n]);
    }
}

// -------------------- scan phase C: recompute with init, emit gated y --------------------
__global__ void scanC(const float* __restrict__ delta, const float* __restrict__ xc,
                      const float* __restrict__ xdb, const float* __restrict__ xz,
                      const float* __restrict__ A_log, const float* __restrict__ Dp,
                      const float* __restrict__ hinit, float* __restrict__ y){
    int wid  = (blockIdx.x*256 + threadIdx.x) >> 5;
    int lane = threadIdx.x & 31;
    int grp = lane >> 4, n = lane & 15;
    if (wid >= 120*NC) return;
    int c  = wid & (NC-1);
    int bd = wid >> 7;
    int b = bd/60, dp = bd - b*60;
    int d = dp*2 + grp;
    float A  = -expf(A_log[d*16 + n]);
    float Dd = Dp[d];
    int idx = (b*120 + d)*NC + c;
    float h = hinit[idx*16 + n];
    size_t row = (size_t)b*LSEQ + (size_t)c*CL;
    const float* pd = delta + row*120 + d;
    const float* px = xc    + row*120 + d;
    const float* pB = xdb   + row*36 + 4  + n;
    const float* pC = xdb   + row*36 + 20 + n;
    const float* pz = xz    + row*240 + 120 + d;
    float* py = y + row*120 + d;
    #pragma unroll 2
    for (int i=0;i<CL;i++){
        float dl = pd[i*120];
        float xv = px[i*120];
        float Bn = pB[i*36];
        float Cn = pC[i*36];
        float a  = __expf(A*dl);
        h = __fmaf_rn(a, h, dl*Bn*xv);
        float t = h * Cn;
        #pragma unroll
        for (int o=8;o;o>>=1) t += __shfl_xor_sync(0xffffffffu, t, o);
        if (n == 0){
            float zv = pz[i*240];
            float sg = 1.f/(1.f + __expf(-zv));
            py[i*120] = (t + Dd*xv) * (zv*sg);
        }
    }
}

// -------------------- 3x3 conv2d (NHWC, C=60) + bias + residual --------------------
__global__ __launch_bounds__(256) void conv2d_res(
    const float* __restrict__ hin, const float* __restrict__ w2,
    const float* __restrict__ b2, const float* __restrict__ x0,
    float* __restrict__ out)
{
    __shared__ float in_s[60][10][10];
    __shared__ __align__(16) float ws[60][64];
    int b  = blockIdx.z;
    int y0 = blockIdx.y*8, xp0 = blockIdx.x*8;
    int tid = threadIdx.x;
    for (int idx = tid; idx < 6000; idx += 256){
        int p = idx/60, ci = idx - p*60;
        int iy = y0 + p/10 - 1, ix = xp0 + (p%10) - 1;
        float v = 0.f;
        if (iy>=0 && iy<128 && ix>=0 && ix<128)
            v = hin[((size_t)b*LSEQ + iy*128 + ix)*60 + ci];
        in_s[ci][p/10][p%10] = v;
    }
    int tn = tid & 15, tm = tid >> 4;
    int py = tm >> 1, pxb = (tm & 1) << 2;
    ull acc[4][2] = {{0ull,0ull},{0ull,0ull},{0ull,0ull},{0ull,0ull}};
    for (int dy=0; dy<3; dy++){
        for (int dx=0; dx<3; dx++){
            __syncthreads();
            for (int idx = tid; idx < 60*64; idx += 256){
                int ci = idx >> 6, o = idx & 63;
                ws[ci][o] = (o < 60) ? w2[((o*60 + ci)*3 + dy)*3 + dx] : 0.f;
            }
            __syncthreads();
            #pragma unroll 4
            for (int ci=0; ci<60; ci++){
                float4 bv = *(const float4*)&ws[ci][tn<<2];
                ull b0 = pk2(bv.x, bv.y);
                ull b1 = pk2(bv.z, bv.w);
                const float* ir = &in_s[ci][py+dy][pxb+dx];
                #pragma unroll
                for (int i=0;i<4;i++){
                    ull ad = pk2(ir[i], ir[i]);
                    fma2(acc[i][0], ad, b0);
                    fma2(acc[i][1], ad, b1);
                }
            }
        }
    }
    #pragma unroll
    for (int i=0;i<4;i++){
        int l = (y0 + py)*128 + xp0 + pxb + i;
        size_t base = ((size_t)b*LSEQ + l)*60;
        #pragma unroll
        for (int jp=0;jp<2;jp++){
            float2 v = upk2(acc[i][jp]);
            int o = (tn<<2) + jp*2;
            if (o   < 60) out[base+o]   = v.x + b2[o]   + x0[base+o];
            if (o+1 < 60) out[base+o+1] = v.y + b2[o+1] + x0[base+o+1];
        }
    }
}

// -------------------- launcher --------------------
extern "C" void kernel_launch(void* const* d_in, const int* in_sizes, int n_in,
                              void* d_out, int out_size)
{
    const float* x     = (const float*)d_in[0];
    const float* ln_w  = (const float*)d_in[1];
    const float* ln_b  = (const float*)d_in[2];
    const float* in_w  = (const float*)d_in[3];
    const float* cw    = (const float*)d_in[4];
    const float* cb    = (const float*)d_in[5];
    const float* xp_w  = (const float*)d_in[6];
    const float* dtw   = (const float*)d_in[7];
    const float* dtb   = (const float*)d_in[8];
    const float* A_log = (const float*)d_in[9];
    const float* Dp    = (const float*)d_in[10];
    const float* ow    = (const float*)d_in[11];
    const float* w2d   = (const float*)d_in[12];
    const float* b2d   = (const float*)d_in[13];
    float* out = (float*)d_out;

    float *p_ln, *p_xz, *p_xc, *p_xdb, *p_delta, *p_y, *p_h, *p_cH, *p_cS, *p_hi;
    cudaGetSymbolAddress((void**)&p_ln,    g_ln);
    cudaGetSymbolAddress((void**)&p_xz,    g_xz);
    cudaGetSymbolAddress((void**)&p_xc,    g_xc);
    cudaGetSymbolAddress((void**)&p_xdb,   g_xdb);
    cudaGetSymbolAddress((void**)&p_delta, g_delta);
    cudaGetSymbolAddress((void**)&p_y,     g_y);
    cudaGetSymbolAddress((void**)&p_h,     g_h);
    cudaGetSymbolAddress((void**)&p_cH,    g_cH);
    cudaGetSymbolAddress((void**)&p_cS,    g_cS);
    cudaGetSymbolAddress((void**)&p_hi,    g_hini);

    const float* layer_in = x;
    for (int i=0;i<2;i++){
        ln_kernel<<<256,256>>>(layer_in, ln_w + i*DM, ln_b + i*DM, p_ln);

        gemm_tn<<<dim3(BL/64, 4), 256>>>(p_ln, in_w + i*240*DM, p_xz, BL, 240, DM);

        conv1d_silu<<<dim3(LSEQ/64, BATCH), 256>>>(p_xz, cw + i*DI*4, cb + i*DI, p_xc);

        gemm_tn<<<dim3(BL/64, 1), 256>>>(p_xc, xp_w + i*36*DI, p_xdb, BL, 36, DI);

        dt_softplus<<<(BL*DI)/256, 256>>>(p_xdb, dtw + i*DI*4, dtb + i*DI, p_delta);

        scanA<<<(120*NC)/8, 256>>>(p_delta, p_xc, p_xdb, A_log + i*DI*DS, p_cH, p_cS);
        scanB<<<15, 256>>>(A_log + i*DI*DS, p_cH, p_cS, p_hi);
        scanC<<<(120*NC)/8, 256>>>(p_delta, p_xc, p_xdb, p_xz,
                                   A_log + i*DI*DS, Dp + i*DI, p_hi, p_y);

        gemm_tn<<<dim3(BL/64, 1), 256>>>(p_y, ow + i*DM*DI, p_h, BL, DM, DI);
        layer_in = p_h;
    }

    conv2d_res<<<dim3(16,16,BATCH), 256>>>(p_h, w2d, b2d, x, out);
}

// round 10
// speedup vs baseline: 1.0027x; 1.0027x over previous
#include <cuda_runtime.h>
#include <cstdint>

#define BATCH 2
#define LSEQ 16384
#define BL (BATCH*LSEQ)      // 32768
#define DM 60
#define DI 120
#define DS 16
#define NC 128               // chunks
#define CL 128               // chunk length (NC*CL == LSEQ)

typedef unsigned long long ull;

// -------------------- scratch (static device memory, ~103 MB) --------------------
__device__ __align__(256) float g_ln   [BL*DM];
__device__ __align__(256) float g_xz   [BL*2*DI];
__device__ __align__(256) float g_xc   [BL*DI];
__device__ __align__(256) float g_xdb  [BL*36];
__device__ __align__(256) float g_delta[BL*DI];
__device__ __align__(256) float g_y    [BL*DI];
__device__ __align__(256) float g_h    [BL*DM];
__device__ __align__(256) float g_cH   [240*NC*16];
__device__ __align__(256) float g_cS   [240*NC];
__device__ __align__(256) float g_hini [240*NC*16];

// -------------------- f32x2 packed helpers --------------------
__device__ __forceinline__ ull pk2(float lo, float hi){
    ull r; asm("mov.b64 %0, {%1, %2};" : "=l"(r) : "f"(lo), "f"(hi)); return r;
}
__device__ __forceinline__ void fma2(ull& d, ull a, ull b){
    asm("fma.rn.f32x2 %0, %1, %2, %3;" : "=l"(d) : "l"(a), "l"(b), "l"(d));
}
__device__ __forceinline__ float2 upk2(ull v){
    float2 r; asm("mov.b64 {%0, %1}, %2;" : "=f"(r.x), "=f"(r.y) : "l"(v)); return r;
}

// -------------------- LayerNorm (warp per row, D=60) --------------------
__global__ void ln_kernel(const float* __restrict__ x, const float* __restrict__ w,
                          const float* __restrict__ b, float* __restrict__ out){
    int gw   = (blockIdx.x*blockDim.x + threadIdx.x) >> 5;
    int lane = threadIdx.x & 31;
    int nw   = (gridDim.x*blockDim.x) >> 5;
    for (int row = gw; row < BL; row += nw){
        const float* xr = x + (size_t)row*DM;
        float v0 = xr[lane];
        float v1 = (lane < DM-32) ? xr[lane+32] : 0.f;
        float s = v0 + v1;
        #pragma unroll
        for (int o=16;o;o>>=1) s += __shfl_xor_sync(0xffffffffu, s, o);
        float mu = s * (1.f/DM);
        float d0 = v0 - mu;
        float d1 = (lane < DM-32) ? (v1 - mu) : 0.f;
        float q = d0*d0 + d1*d1;
        #pragma unroll
        for (int o=16;o;o>>=1) q += __shfl_xor_sync(0xffffffffu, q, o);
        float rs = rsqrtf(q*(1.f/DM) + 1e-5f);
        float* orow = out + (size_t)row*DM;
        orow[lane] = d0*rs*w[lane] + b[lane];
        if (lane < DM-32) orow[lane+32] = d1*rs*w[lane+32] + b[lane+32];
    }
}

// -------------------- GEMM:  Y[M,N] = X[M,K] @ W[N,K]^T  --------------------
// 64x64 block tile, BK=16, 256 threads, 4x4 microtile, f32x2 FMA.
__global__ __launch_bounds__(256) void gemm_tn(
    const float* __restrict__ X, const float* __restrict__ W,
    float* __restrict__ Y, int M, int N, int K)
{
    __shared__ __align__(16) float xs[16][68];
    __shared__ __align__(16) float ws[16][68];
    int bm = blockIdx.x*64, bn = blockIdx.y*64;
    int tid = threadIdx.x;
    int tn = tid & 15, tm = tid >> 4;
    int r  = tid >> 2, kq = (tid & 3) << 2;
    ull acc[4][2] = {{0ull,0ull},{0ull,0ull},{0ull,0ull},{0ull,0ull}};

    for (int k0 = 0; k0 < K; k0 += 16){
        int gk = k0 + kq;
        float4 vx = make_float4(0.f,0.f,0.f,0.f);
        float4 vw = make_float4(0.f,0.f,0.f,0.f);
        int gm = bm + r;
        if (gm < M){
            const float* p = X + (size_t)gm*K + gk;
            if (gk + 3 < K) vx = *(const float4*)p;
            else {
                if (gk   < K) vx.x = p[0];
                if (gk+1 < K) vx.y = p[1];
                if (gk+2 < K) vx.z = p[2];
                if (gk+3 < K) vx.w = p[3];
            }
        }
        int gn = bn + r;
        if (gn < N){
            const float* p = W + (size_t)gn*K + gk;
            if (gk + 3 < K) vw = *(const float4*)p;
            else {
                if (gk   < K) vw.x = p[0];
                if (gk+1 < K) vw.y = p[1];
                if (gk+2 < K) vw.z = p[2];
                if (gk+3 < K) vw.w = p[3];
            }
        }
        __syncthreads();
        xs[kq+0][r]=vx.x; xs[kq+1][r]=vx.y; xs[kq+2][r]=vx.z; xs[kq+3][r]=vx.w;
        ws[kq+0][r]=vw.x; ws[kq+1][r]=vw.y; ws[kq+2][r]=vw.z; ws[kq+3][r]=vw.w;
        __syncthreads();
        #pragma unroll
        for (int kk=0; kk<16; kk++){
            float4 av = *(const float4*)&xs[kk][tm<<2];
            float4 bv = *(const float4*)&ws[kk][tn<<2];
            ull b0 = pk2(bv.x, bv.y);
            ull b1 = pk2(bv.z, bv.w);
            float a_[4] = {av.x, av.y, av.z, av.w};
            #pragma unroll
            for (int i=0;i<4;i++){
                ull ad = pk2(a_[i], a_[i]);
                fma2(acc[i][0], ad, b0);
                fma2(acc[i][1], ad, b1);
            }
        }
    }
    #pragma unroll
    for (int i=0;i<4;i++){
        int gm = bm + (tm<<2) + i;
        if (gm >= M) continue;
        float* yr = Y + (size_t)gm*N;
        #pragma unroll
        for (int jp=0;jp<2;jp++){
            float2 v = upk2(acc[i][jp]);
            int c0 = bn + (tn<<2) + jp*2;
            if (c0   < N) yr[c0]   = v.x;
            if (c0+1 < N) yr[c0+1] = v.y;
        }
    }
}

// -------------------- causal depthwise conv1d (D_CONV=4) + bias + SiLU --------------------
__global__ void conv1d_silu(const float* __restrict__ xz, const float* __restrict__ cw,
                            const float* __restrict__ cb, float* __restrict__ xc){
    __shared__ float s[67][120];
    int b = blockIdx.y;
    int start = blockIdx.x * 64;
    for (int idx = threadIdx.x; idx < 67*120; idx += 256){
        int j = idx/120, d = idx - j*120;
        int l = start + j - 3;
        s[j][d] = (l >= 0) ? xz[((size_t)(b*LSEQ + l))*240 + d] : 0.f;
    }
    __syncthreads();
    for (int idx = threadIdx.x; idx < 64*120; idx += 256){
        int i = idx/120, d = idx - i*120;
        const float* w = cw + d*4;
        float a = cb[d] + s[i][d]*w[0] + s[i+1][d]*w[1] + s[i+2][d]*w[2] + s[i+3][d]*w[3];
        float sg = 1.f/(1.f + __expf(-a));
        xc[((size_t)(b*LSEQ + start + i))*120 + d] = a*sg;
    }
}

// -------------------- dt projection + softplus --------------------
__global__ void dt_softplus(const float* __restrict__ xdb, const float* __restrict__ dtw,
                            const float* __restrict__ dtb, float* __restrict__ delta){
    int idx = blockIdx.x*256 + threadIdx.x;
    if (idx >= BL*120) return;
    int row = idx/120, d = idx - row*120;
    const float* xr = xdb + (size_t)row*36;
    float4 w = *(const float4*)(dtw + d*4);
    float sv = dtb[d] + xr[0]*w.x + xr[1]*w.y + xr[2]*w.z + xr[3]*w.w;
    delta[idx] = (sv > 20.f) ? sv : log1pf(__expf(sv));
}

// -------------------- selective scan, phase A: per-chunk local scan --------------------
// Warp layout: two 16-lane groups handle channels d=2p and d=2p+1 (same batch, same chunk),
// lane%16 = state index n.  Stores chunk-final h and sum(delta) over the chunk.
__global__ void scanA(const float* __restrict__ delta, const float* __restrict__ xc,
                      const float* __restrict__ xdb, const float* __restrict__ A_log,
                      float* __restrict__ cH, float* __restrict__ cS){
    int wid  = (blockIdx.x*256 + threadIdx.x) >> 5;
    int lane = threadIdx.x & 31;
    int grp = lane >> 4, n = lane & 15;
    if (wid >= 120*NC) return;
    int c  = wid & (NC-1);
    int bd = wid >> 7;                 // NC == 128
    int b = bd/60, dp = bd - b*60;
    int d = dp*2 + grp;
    float A = -expf(A_log[d*16 + n]);
    float h = 0.f, sd = 0.f;
    size_t row = (size_t)b*LSEQ + (size_t)c*CL;
    const float* pd = delta + row*120 + d;
    const float* px = xc    + row*120 + d;
    const float* pB = xdb   + row*36 + 4 + n;
    #pragma unroll 4
    for (int i=0;i<CL;i++){
        float dl = pd[i*120];
        float xv = px[i*120];
        float Bn = pB[i*36];
        float a  = __expf(A*dl);
        h  = __fmaf_rn(a, h, dl*Bn*xv);
        sd += dl;
    }
    int idx = (b*120 + d)*NC + c;
    cH[idx*16 + n] = h;
    if (n == 0) cS[idx] = sd;
}

// -------------------- scan phase B: cross-chunk prefix (tiny) --------------------
__global__ void scanB(const float* __restrict__ A_log, const float* __restrict__ cH,
                      const float* __restrict__ cS, float* __restrict__ hinit){
    int wid  = (blockIdx.x*256 + threadIdx.x) >> 5;
    int lane = threadIdx.x & 31;
    int grp = lane >> 4, n = lane & 15;
    if (wid >= 120) return;
    int b = wid/60, dp = wid - b*60;
    int d = dp*2 + grp;
    float A = -expf(A_log[d*16 + n]);
    float h = 0.f;
    int base = (b*120 + d)*NC;
    for (int c=0;c<NC;c++){
        hinit[(base+c)*16 + n] = h;
        float P = __expf(A * cS[base+c]);
        h = __fmaf_rn(P, h, cH[(base+c)*16 + n]);
    }
}

// -------------------- scan phase C: recompute with init, emit gated y --------------------
__global__ void scanC(const float* __restrict__ delta, const float* __restrict__ xc,
                      const float* __restrict__ xdb, const float* __restrict__ xz,
                      const float* __restrict__ A_log, const float* __restrict__ Dp,
                      const float* __restrict__ hinit, float* __restrict__ y){
    int wid  = (blockIdx.x*256 + threadIdx.x) >> 5;
    int lane = threadIdx.x & 31;
    int grp = lane >> 4, n = lane & 15;
    if (wid >= 120*NC) return;
    int c  = wid & (NC-1);
    int bd = wid >> 7;
    int b = bd/60, dp = bd - b*60;
    int d = dp*2 + grp;
    float A  = -expf(A_log[d*16 + n]);
    float Dd = Dp[d];
    int idx = (b*120 + d)*NC + c;
    float h = hinit[idx*16 + n];
    size_t row = (size_t)b*LSEQ + (size_t)c*CL;
    const float* pd = delta + row*120 + d;
    const float* px = xc    + row*120 + d;
    const float* pB = xdb   + row*36 + 4  + n;
    const float* pC = xdb   + row*36 + 20 + n;
    const float* pz = xz    + row*240 + 120 + d;
    float* py = y + row*120 + d;
    #pragma unroll 2
    for (int i=0;i<CL;i++){
        float dl = pd[i*120];
        float xv = px[i*120];
        float Bn = pB[i*36];
        float Cn = pC[i*36];
        float a  = __expf(A*dl);
        h = __fmaf_rn(a, h, dl*Bn*xv);
        float t = h * Cn;
        #pragma unroll
        for (int o=8;o;o>>=1) t += __shfl_xor_sync(0xffffffffu, t, o);
        if (n == 0){
            float zv = pz[i*240];
            float sg = 1.f/(1.f + __expf(-zv));
            py[i*120] = (t + Dd*xv) * (zv*sg);
        }
    }
}

// -------------------- 3x3 conv2d (NHWC, C=60) + bias + residual --------------------
__global__ __launch_bounds__(256) void conv2d_res(
    const float* __restrict__ hin, const float* __restrict__ w2,
    const float* __restrict__ b2, const float* __restrict__ x0,
    float* __restrict__ out)
{
    __shared__ float in_s[60][10][10];
    __shared__ __align__(16) float ws[60][64];
    int b  = blockIdx.z;
    int y0 = blockIdx.y*8, xp0 = blockIdx.x*8;
    int tid = threadIdx.x;
    for (int idx = tid; idx < 6000; idx += 256){
        int p = idx/60, ci = idx - p*60;
        int iy = y0 + p/10 - 1, ix = xp0 + (p%10) - 1;
        float v = 0.f;
        if (iy>=0 && iy<128 && ix>=0 && ix<128)
            v = hin[((size_t)b*LSEQ + iy*128 + ix)*60 + ci];
        in_s[ci][p/10][p%10] = v;
    }
    int tn = tid & 15, tm = tid >> 4;
    int py = tm >> 1, pxb = (tm & 1) << 2;
    ull acc[4][2] = {{0ull,0ull},{0ull,0ull},{0ull,0ull},{0ull,0ull}};
    for (int dy=0; dy<3; dy++){
        for (int dx=0; dx<3; dx++){
            __syncthreads();
            for (int idx = tid; idx < 60*64; idx += 256){
                int ci = idx >> 6, o = idx & 63;
                ws[ci][o] = (o < 60) ? w2[((o*60 + ci)*3 + dy)*3 + dx] : 0.f;
            }
            __syncthreads();
            #pragma unroll 4
            for (int ci=0; ci<60; ci++){
                float4 bv = *(const float4*)&ws[ci][tn<<2];
                ull b0 = pk2(bv.x, bv.y);
                ull b1 = pk2(bv.z, bv.w);
                const float* ir = &in_s[ci][py+dy][pxb+dx];
                #pragma unroll
                for (int i=0;i<4;i++){
                    ull ad = pk2(ir[i], ir[i]);
                    fma2(acc[i][0], ad, b0);
                    fma2(acc[i][1], ad, b1);
                }
            }
        }
    }
    #pragma unroll
    for (int i=0;i<4;i++){
        int l = (y0 + py)*128 + xp0 + pxb + i;
        size_t base = ((size_t)b*LSEQ + l)*60;
        #pragma unroll
        for (int jp=0;jp<2;jp++){
            float2 v = upk2(acc[i][jp]);
            int o = (tn<<2) + jp*2;
            if (o   < 60) out[base+o]   = v.x + b2[o]   + x0[base+o];
            if (o+1 < 60) out[base+o+1] = v.y + b2[o+1] + x0[base+o+1];
        }
    }
}

// -------------------- launcher --------------------
extern "C" void kernel_launch(void* const* d_in, const int* in_sizes, int n_in,
                              void* d_out, int out_size)
{
    const float* x     = (const float*)d_in[0];
    const float* ln_w  = (const float*)d_in[1];
    const float* ln_b  = (const float*)d_in[2];
    const float* in_w  = (const float*)d_in[3];
    const float* cw    = (const float*)d_in[4];
    const float* cb    = (const float*)d_in[5];
    const float* xp_w  = (const float*)d_in[6];
    const float* dtw   = (const float*)d_in[7];
    const float* dtb   = (const float*)d_in[8];
    const float* A_log = (const float*)d_in[9];
    const float* Dp    = (const float*)d_in[10];
    const float* ow    = (const float*)d_in[11];
    const float* w2d   = (const float*)d_in[12];
    const float* b2d   = (const float*)d_in[13];
    float* out = (float*)d_out;

    float *p_ln, *p_xz, *p_xc, *p_xdb, *p_delta, *p_y, *p_h, *p_cH, *p_cS, *p_hi;
    cudaGetSymbolAddress((void**)&p_ln,    g_ln);
    cudaGetSymbolAddress((void**)&p_xz,    g_xz);
    cudaGetSymbolAddress((void**)&p_xc,    g_xc);
    cudaGetSymbolAddress((void**)&p_xdb,   g_xdb);
    cudaGetSymbolAddress((void**)&p_delta, g_delta);
    cudaGetSymbolAddress((void**)&p_y,     g_y);
    cudaGetSymbolAddress((void**)&p_h,     g_h);
    cudaGetSymbolAddress((void**)&p_cH,    g_cH);
    cudaGetSymbolAddress((void**)&p_cS,    g_cS);
    cudaGetSymbolAddress((void**)&p_hi,    g_hini);

    const float* layer_in = x;
    for (int i=0;i<2;i++){
        ln_kernel<<<256,256>>>(layer_in, ln_w + i*DM, ln_b + i*DM, p_ln);

        gemm_tn<<<dim3(BL/64, 4), 256>>>(p_ln, in_w + i*240*DM, p_xz, BL, 240, DM);

        conv1d_silu<<<dim3(LSEQ/64, BATCH), 256>>>(p_xz, cw + i*DI*4, cb + i*DI, p_xc);

        gemm_tn<<<dim3(BL/64, 1), 256>>>(p_xc, xp_w + i*36*DI, p_xdb, BL, 36, DI);

        dt_softplus<<<(BL*DI)/256, 256>>>(p_xdb, dtw + i*DI*4, dtb + i*DI, p_delta);

        scanA<<<(120*NC)/8, 256>>>(p_delta, p_xc, p_xdb, A_log + i*DI*DS, p_cH, p_cS);
        scanB<<<15, 256>>>(A_log + i*DI*DS, p_cH, p_cS, p_hi);
        scanC<<<(120*NC)/8, 256>>>(p_delta, p_xc, p_xdb, p_xz,
                                   A_log + i*DI*DS, Dp + i*DI, p_hi, p_y);

        gemm_tn<<<dim3(BL/64, 1), 256>>>(p_y, ow + i*DM*DI, p_h, BL, DM, DI);
        layer_in = p_h;
    }

    conv2d_res<<<dim3(16,16,BATCH), 256>>>(p_h, w2d, b2d, x, out);
}